// round 13
// baseline (speedup 1.0000x reference)
#include <cuda_runtime.h>
#include <cuda_bf16.h>
#include <cuda_fp16.h>

#define NMAX 100000
#define EMAX 1250000
#define DD 64

// ---------------- scratch ----------------
__device__ int    g_degi[NMAX];
__device__ float  g_dis[NMAX];
__device__ int    g_rowptr[NMAX + 1];
__device__ int    g_cursor[NMAX];
__device__ int    g_csr[EMAX];
__device__ int    g_scan_ctr;
__device__ int    g_agg[256];
__device__ int    g_incl[256];
__device__ int    g_stat[256];
__device__ __half g_hA[(size_t)NMAX * DD];
__device__ __half g_hB[(size_t)NMAX * DD];
__device__ __half g_hC[(size_t)NMAX * DD];
__device__ __half g_hM[(size_t)NMAX * DD];

// ---------------- fp16 mma helper ----------------
__device__ __forceinline__ void mma16(float c[4], unsigned a0, unsigned a1, unsigned a2,
                                      unsigned a3, unsigned b0, unsigned b1) {
    asm("mma.sync.aligned.m16n8k16.row.col.f32.f16.f16.f32 "
        "{%0,%1,%2,%3},{%4,%5,%6,%7},{%8,%9},{%0,%1,%2,%3};"
        : "+f"(c[0]), "+f"(c[1]), "+f"(c[2]), "+f"(c[3])
        : "r"(a0), "r"(a1), "r"(a2), "r"(a3), "r"(b0), "r"(b1));
}

__device__ __forceinline__ void acc8s(float4& a, float4& b, uint4 u) {
    float2 f0 = __half22float2(*reinterpret_cast<const __half2*>(&u.x));
    float2 f1 = __half22float2(*reinterpret_cast<const __half2*>(&u.y));
    float2 f2 = __half22float2(*reinterpret_cast<const __half2*>(&u.z));
    float2 f3 = __half22float2(*reinterpret_cast<const __half2*>(&u.w));
    a.x += f0.x; a.y += f0.y; a.z += f1.x; a.w += f1.y;
    b.x += f2.x; b.y += f2.y; b.z += f3.x; b.w += f3.y;
}
__device__ __forceinline__ unsigned packh2(float x, float y) {
    __half2 h = __floats2half2_rn(x, y);
    return *reinterpret_cast<unsigned*>(&h);
}
__device__ __forceinline__ uint4 pack_h8(float4 a, float4 b) {
    uint4 u;
    u.x = packh2(a.x, a.y); u.y = packh2(a.z, a.w);
    u.z = packh2(b.x, b.y); u.w = packh2(b.z, b.w);
    return u;
}
__device__ __forceinline__ uint2 pack_h4(float4 v) {
    uint2 u;
    u.x = packh2(v.x, v.y); u.y = packh2(v.z, v.w);
    return u;
}

// ---------------- degree ----------------
__global__ void deg_count_kernel(const int* __restrict__ dst, int E, int* __restrict__ degi) {
    int i = blockIdx.x * blockDim.x + threadIdx.x;
    if (i < E) atomicAdd(&degi[dst[i]], 1);
}

// ---------------- single-pass decoupled-lookback exclusive scan + dis ----------------
__global__ void scan_lb_kernel(const int* __restrict__ cnt, int* __restrict__ rowptr,
                               int* __restrict__ cursor, float* __restrict__ dis,
                               int n, int E) {
    __shared__ int s[512];
    __shared__ int sbid, sprefix;
    int tid = threadIdx.x;
    if (tid == 0) sbid = atomicAdd(&g_scan_ctr, 1);
    __syncthreads();
    int bid = sbid;
    int i = bid * 512 + tid;
    int v = (i < n) ? cnt[i] : 0;
    if (i < n) dis[i] = rsqrtf((float)v + 1.0f);
    s[tid] = v;
    __syncthreads();
    for (int off = 1; off < 512; off <<= 1) {
        int t = (tid >= off) ? s[tid - off] : 0;
        __syncthreads();
        s[tid] += t;
        __syncthreads();
    }
    int total = s[511];
    if (tid == 0) {
        g_agg[bid] = total;
        __threadfence();
        g_stat[bid] = 1;
        int sum = 0;
        int j = bid - 1;
        while (j >= 0) {
            int st;
            do { st = ((volatile int*)g_stat)[j]; } while (st == 0);
            __threadfence();
            if (st == 2) { sum += ((volatile int*)g_incl)[j]; break; }
            sum += ((volatile int*)g_agg)[j];
            j--;
        }
        g_incl[bid] = sum + total;
        __threadfence();
        g_stat[bid] = 2;
        sprefix = sum;
    }
    __syncthreads();
    int prefix = sprefix;
    if (i < n) {
        int ex = prefix + s[tid] - v;
        rowptr[i] = ex;
        cursor[i] = ex;
    }
    if (i == n - 1) rowptr[n] = E;
}

__global__ void fill_csr_kernel(const int* __restrict__ src, const int* __restrict__ dst,
                                int* __restrict__ cursor, int* __restrict__ csr, int E) {
    int i = blockIdx.x * blockDim.x + threadIdx.x;
    if (i < E) {
        int pos = atomicAdd(&cursor[dst[i]], 1);
        csr[pos] = src[i];
    }
}

// ---------------- gather (CSR), 8 lanes/node, int4 csr, [nodeBeg, nodeBeg+cnt) ----------------
// GCN=true : input rows prescaled z=xw*dis. out = relu?((sum_s z[s] + z[d]) * dis[d] + bias)
// GCN=false: out = (sum_s h[s]) / max(deg,1)
template <bool GCN, bool RELU, bool OUTF32>
__global__ void __launch_bounds__(256) gather_kernel(
    const int* __restrict__ rowptr, const int* __restrict__ csr,
    const __half* __restrict__ xwh, const float* __restrict__ dis,
    const float* __restrict__ bias, float* __restrict__ outf,
    __half* __restrict__ outh, int nodeBeg, int nodeCnt) {
    int local = blockIdx.x * 32 + (threadIdx.x >> 3);
    int q = threadIdx.x & 7;
    if (local >= nodeCnt) return;
    int node = nodeBeg + local;
    int beg = rowptr[node], end = rowptr[node + 1];
    float4 aL = make_float4(0.f, 0.f, 0.f, 0.f);
    float4 aH = make_float4(0.f, 0.f, 0.f, 0.f);
    const uint4* __restrict__ xv4 = (const uint4*)xwh;
    int e = beg;
    while (e < end && (e & 3)) { acc8s(aL, aH, xv4[csr[e] * 8 + q]); e++; }
    for (; e + 3 < end; e += 4) {
        int4 s4 = *reinterpret_cast<const int4*>(csr + e);
        uint4 u0 = xv4[s4.x * 8 + q];
        uint4 u1 = xv4[s4.y * 8 + q];
        uint4 u2 = xv4[s4.z * 8 + q];
        uint4 u3 = xv4[s4.w * 8 + q];
        acc8s(aL, aH, u0); acc8s(aL, aH, u1);
        acc8s(aL, aH, u2); acc8s(aL, aH, u3);
    }
    for (; e < end; e++) acc8s(aL, aH, xv4[csr[e] * 8 + q]);

    if (GCN) {
        acc8s(aL, aH, xv4[node * 8 + q]);
        float dd = dis[node];
        float4 b0 = ((const float4*)bias)[q * 2];
        float4 b1 = ((const float4*)bias)[q * 2 + 1];
        aL.x = fmaf(aL.x, dd, b0.x); aL.y = fmaf(aL.y, dd, b0.y);
        aL.z = fmaf(aL.z, dd, b0.z); aL.w = fmaf(aL.w, dd, b0.w);
        aH.x = fmaf(aH.x, dd, b1.x); aH.y = fmaf(aH.y, dd, b1.y);
        aH.z = fmaf(aH.z, dd, b1.z); aH.w = fmaf(aH.w, dd, b1.w);
        if (RELU) {
            aL.x = fmaxf(aL.x, 0.f); aL.y = fmaxf(aL.y, 0.f);
            aL.z = fmaxf(aL.z, 0.f); aL.w = fmaxf(aL.w, 0.f);
            aH.x = fmaxf(aH.x, 0.f); aH.y = fmaxf(aH.y, 0.f);
            aH.z = fmaxf(aH.z, 0.f); aH.w = fmaxf(aH.w, 0.f);
        }
    } else {
        float dinv = 1.0f / fmaxf((float)(end - beg), 1.0f);
        aL.x *= dinv; aL.y *= dinv; aL.z *= dinv; aL.w *= dinv;
        aH.x *= dinv; aH.y *= dinv; aH.z *= dinv; aH.w *= dinv;
    }
    if (OUTF32) {
        ((float4*)outf)[node * 16 + q * 2]     = aL;
        ((float4*)outf)[node * 16 + q * 2 + 1] = aH;
    } else {
        ((uint4*)outh)[node * 8 + q] = pack_h8(aL, aH);
    }
}

// ---------------- fp16 tensor-core GEMM: out = act(X @ W [+ b]) [* dis] -> fp16 ----------------
template <bool RELU, bool BIAS, bool PRESCALE>
__global__ void __launch_bounds__(256) gemm_h_kernel(
    const float* __restrict__ Xf, const float* __restrict__ W,
    const float* __restrict__ bias, const float* __restrict__ dis,
    __half* __restrict__ outh, int n) {
    __shared__ __half Wt[64 * 72];
    __shared__ __half Xh[128 * 72];
    int tid = threadIdx.x;
    int row0 = blockIdx.x * 128;

    for (int i = tid; i < 4096; i += 256) {
        int k = i >> 6, c = i & 63;
        Wt[c * 72 + k] = __float2half(W[i]);
    }
    for (int j = tid; j < 2048; j += 256) {
        int r = j >> 4, cg = j & 15;
        uint2 u = make_uint2(0u, 0u);
        if (row0 + r < n) {
            float4 v = ((const float4*)Xf)[(size_t)(row0 + r) * 16 + cg];
            u = pack_h4(v);
        }
        *reinterpret_cast<uint2*>(&Xh[r * 72 + cg * 4]) = u;
    }
    __syncthreads();

    int warp = tid >> 5;
    int lane = tid & 31;
    int gid = lane >> 2;
    int tig = lane & 3;
    int rlo = warp * 16 + gid;

    float c[8][4];
#pragma unroll
    for (int t = 0; t < 8; t++)
#pragma unroll
        for (int j = 0; j < 4; j++) c[t][j] = 0.f;

#pragma unroll
    for (int ks = 0; ks < 4; ks++) {
        int k0 = ks * 16;
        unsigned a0 = *reinterpret_cast<const unsigned*>(&Xh[rlo * 72 + k0 + tig * 2]);
        unsigned a1 = *reinterpret_cast<const unsigned*>(&Xh[(rlo + 8) * 72 + k0 + tig * 2]);
        unsigned a2 = *reinterpret_cast<const unsigned*>(&Xh[rlo * 72 + k0 + 8 + tig * 2]);
        unsigned a3 = *reinterpret_cast<const unsigned*>(&Xh[(rlo + 8) * 72 + k0 + 8 + tig * 2]);
#pragma unroll
        for (int t = 0; t < 8; t++) {
            int col = t * 8 + gid;
            unsigned b0 = *reinterpret_cast<const unsigned*>(&Wt[col * 72 + k0 + tig * 2]);
            unsigned b1 = *reinterpret_cast<const unsigned*>(&Wt[col * 72 + k0 + 8 + tig * 2]);
            mma16(c[t], a0, a1, a2, a3, b0, b1);
        }
    }

    int row_lo = row0 + warp * 16 + gid;
    int row_hi = row_lo + 8;
    float dd_lo = 1.f, dd_hi = 1.f;
    if (PRESCALE) {
        if (row_lo < n) dd_lo = dis[row_lo];
        if (row_hi < n) dd_hi = dis[row_hi];
    }
#pragma unroll
    for (int t = 0; t < 8; t++) {
        int colp = t * 4 + tig;
        float2 bb = BIAS ? ((const float2*)bias)[colp] : make_float2(0.f, 0.f);
        if (row_lo < n) {
            float ox = c[t][0] + bb.x, oy = c[t][1] + bb.y;
            if (RELU) { ox = fmaxf(ox, 0.f); oy = fmaxf(oy, 0.f); }
            if (PRESCALE) { ox *= dd_lo; oy *= dd_lo; }
            ((__half2*)outh)[(size_t)row_lo * 32 + colp] = __floats2half2_rn(ox, oy);
        }
        if (row_hi < n) {
            float ox = c[t][2] + bb.x, oy = c[t][3] + bb.y;
            if (RELU) { ox = fmaxf(ox, 0.f); oy = fmaxf(oy, 0.f); }
            if (PRESCALE) { ox *= dd_hi; oy *= dd_hi; }
            ((__half2*)outh)[(size_t)row_hi * 32 + colp] = __floats2half2_rn(ox, oy);
        }
    }
}

// ---------------- fp16 SAGE (rows [rowBeg, rowBeg+rowCnt)): act(M@Wl + bl + H@Wr + H) ----------------
template <bool RELU>
__global__ void __launch_bounds__(256) sage_h_kernel(
    const __half* __restrict__ M, const __half* __restrict__ H,
    const float* __restrict__ Wl, const float* __restrict__ bl,
    const float* __restrict__ Wr, __half* __restrict__ outh,
    int rowBeg, int rowCnt, int n) {
    extern __shared__ char smraw[];
    __half* Wc = (__half*)smraw;                    // [64 cols][136 k]
    __half* Mh = (__half*)(smraw + 17408);          // [128][72]
    __half* Hh = (__half*)(smraw + 17408 + 18432);  // [128][72]
    int tid = threadIdx.x;
    int row0 = rowBeg + blockIdx.x * 128;
    int rowLim = rowBeg + rowCnt;
    if (rowLim > n) rowLim = n;

    for (int i = tid; i < 4096; i += 256) {
        int k = i >> 6, cc = i & 63;
        Wc[cc * 136 + k]      = __float2half(Wl[i]);
        Wc[cc * 136 + 64 + k] = __float2half(Wr[i]);
    }
    for (int j = tid; j < 2048; j += 256) {
        int r = j >> 4, cg = j & 15;
        uint2 um = make_uint2(0u, 0u), uh = um;
        if (row0 + r < rowLim) {
            um = ((const uint2*)M)[(size_t)(row0 + r) * 16 + cg];
            uh = ((const uint2*)H)[(size_t)(row0 + r) * 16 + cg];
        }
        *reinterpret_cast<uint2*>(&Mh[r * 72 + cg * 4]) = um;
        *reinterpret_cast<uint2*>(&Hh[r * 72 + cg * 4]) = uh;
    }
    __syncthreads();

    int warp = tid >> 5;
    int lane = tid & 31;
    int gid = lane >> 2;
    int tig = lane & 3;
    int rlo = warp * 16 + gid;

    float c[8][4];
#pragma unroll
    for (int t = 0; t < 8; t++)
#pragma unroll
        for (int j = 0; j < 4; j++) c[t][j] = 0.f;

#pragma unroll
    for (int ks = 0; ks < 8; ks++) {
        const __half* A = (ks < 4) ? Mh : Hh;
        int k0 = (ks & 3) * 16;
        int kw = ks * 16;
        unsigned a0 = *reinterpret_cast<const unsigned*>(&A[rlo * 72 + k0 + tig * 2]);
        unsigned a1 = *reinterpret_cast<const unsigned*>(&A[(rlo + 8) * 72 + k0 + tig * 2]);
        unsigned a2 = *reinterpret_cast<const unsigned*>(&A[rlo * 72 + k0 + 8 + tig * 2]);
        unsigned a3 = *reinterpret_cast<const unsigned*>(&A[(rlo + 8) * 72 + k0 + 8 + tig * 2]);
#pragma unroll
        for (int t = 0; t < 8; t++) {
            int col = t * 8 + gid;
            unsigned b0 = *reinterpret_cast<const unsigned*>(&Wc[col * 136 + kw + tig * 2]);
            unsigned b1 = *reinterpret_cast<const unsigned*>(&Wc[col * 136 + kw + 8 + tig * 2]);
            mma16(c[t], a0, a1, a2, a3, b0, b1);
        }
    }

#pragma unroll
    for (int t = 0; t < 8; t++) {
        int colp = t * 4 + tig;
        int col = t * 8 + tig * 2;
        float2 bb = ((const float2*)bl)[colp];
        int rl = warp * 16 + gid;
        int row_lo = row0 + rl;
        int row_hi = row_lo + 8;
        if (row_lo < rowLim) {
            float2 hres = __half22float2(*reinterpret_cast<const __half2*>(&Hh[rl * 72 + col]));
            float ox = c[t][0] + bb.x + hres.x, oy = c[t][1] + bb.y + hres.y;
            if (RELU) { ox = fmaxf(ox, 0.f); oy = fmaxf(oy, 0.f); }
            ((__half2*)outh)[(size_t)row_lo * 32 + colp] = __floats2half2_rn(ox, oy);
        }
        if (row_hi < rowLim) {
            float2 hres = __half22float2(*reinterpret_cast<const __half2*>(&Hh[(rl + 8) * 72 + col]));
            float ox = c[t][2] + bb.x + hres.x, oy = c[t][3] + bb.y + hres.y;
            if (RELU) { ox = fmaxf(ox, 0.f); oy = fmaxf(oy, 0.f); }
            ((__half2*)outh)[(size_t)row_hi * 32 + colp] = __floats2half2_rn(ox, oy);
        }
    }
}

// ---------------- fused lin+gcn2: out = ((relu(X@W1 + b1)) @ W2) * dis -> fp16 ----------------
__global__ void __launch_bounds__(256) lin_gcn2_kernel(
    const __half* __restrict__ Xin, const float* __restrict__ W1,
    const float* __restrict__ b1, const float* __restrict__ W2,
    const float* __restrict__ dis, __half* __restrict__ outh, int n) {
    extern __shared__ char smraw[];
    __half* W1t = (__half*)smraw;
    __half* W2t = (__half*)(smraw + 9216);
    __half* Xh  = (__half*)(smraw + 18432);
    __half* Th  = (__half*)(smraw + 18432 + 18432);
    int tid = threadIdx.x;
    int row0 = blockIdx.x * 128;

    for (int i = tid; i < 4096; i += 256) {
        int k = i >> 6, cc = i & 63;
        W1t[cc * 72 + k] = __float2half(W1[i]);
        W2t[cc * 72 + k] = __float2half(W2[i]);
    }
    for (int j = tid; j < 2048; j += 256) {
        int r = j >> 4, cg = j & 15;
        uint2 u = make_uint2(0u, 0u);
        if (row0 + r < n) u = ((const uint2*)Xin)[(size_t)(row0 + r) * 16 + cg];
        *reinterpret_cast<uint2*>(&Xh[r * 72 + cg * 4]) = u;
    }
    __syncthreads();

    int warp = tid >> 5;
    int lane = tid & 31;
    int gid = lane >> 2;
    int tig = lane & 3;
    int rlo = warp * 16 + gid;

    float c[8][4];
#pragma unroll
    for (int t = 0; t < 8; t++)
#pragma unroll
        for (int j = 0; j < 4; j++) c[t][j] = 0.f;

#pragma unroll
    for (int ks = 0; ks < 4; ks++) {
        int k0 = ks * 16;
        unsigned a0 = *reinterpret_cast<const unsigned*>(&Xh[rlo * 72 + k0 + tig * 2]);
        unsigned a1 = *reinterpret_cast<const unsigned*>(&Xh[(rlo + 8) * 72 + k0 + tig * 2]);
        unsigned a2 = *reinterpret_cast<const unsigned*>(&Xh[rlo * 72 + k0 + 8 + tig * 2]);
        unsigned a3 = *reinterpret_cast<const unsigned*>(&Xh[(rlo + 8) * 72 + k0 + 8 + tig * 2]);
#pragma unroll
        for (int t = 0; t < 8; t++) {
            int col = t * 8 + gid;
            unsigned b0 = *reinterpret_cast<const unsigned*>(&W1t[col * 72 + k0 + tig * 2]);
            unsigned b1 = *reinterpret_cast<const unsigned*>(&W1t[col * 72 + k0 + 8 + tig * 2]);
            mma16(c[t], a0, a1, a2, a3, b0, b1);
        }
    }
#pragma unroll
    for (int t = 0; t < 8; t++) {
        int colp = t * 4 + tig;
        int col = t * 8 + tig * 2;
        float2 bb = ((const float2*)b1)[colp];
        int rl = warp * 16 + gid;
        float ox0 = fmaxf(c[t][0] + bb.x, 0.f), oy0 = fmaxf(c[t][1] + bb.y, 0.f);
        float ox1 = fmaxf(c[t][2] + bb.x, 0.f), oy1 = fmaxf(c[t][3] + bb.y, 0.f);
        *reinterpret_cast<__half2*>(&Th[rl * 72 + col])       = __floats2half2_rn(ox0, oy0);
        *reinterpret_cast<__half2*>(&Th[(rl + 8) * 72 + col]) = __floats2half2_rn(ox1, oy1);
    }
    __syncthreads();

#pragma unroll
    for (int t = 0; t < 8; t++)
#pragma unroll
        for (int j = 0; j < 4; j++) c[t][j] = 0.f;
#pragma unroll
    for (int ks = 0; ks < 4; ks++) {
        int k0 = ks * 16;
        unsigned a0 = *reinterpret_cast<const unsigned*>(&Th[rlo * 72 + k0 + tig * 2]);
        unsigned a1 = *reinterpret_cast<const unsigned*>(&Th[(rlo + 8) * 72 + k0 + tig * 2]);
        unsigned a2 = *reinterpret_cast<const unsigned*>(&Th[rlo * 72 + k0 + 8 + tig * 2]);
        unsigned a3 = *reinterpret_cast<const unsigned*>(&Th[(rlo + 8) * 72 + k0 + 8 + tig * 2]);
#pragma unroll
        for (int t = 0; t < 8; t++) {
            int col = t * 8 + gid;
            unsigned b0 = *reinterpret_cast<const unsigned*>(&W2t[col * 72 + k0 + tig * 2]);
            unsigned b1 = *reinterpret_cast<const unsigned*>(&W2t[col * 72 + k0 + 8 + tig * 2]);
            mma16(c[t], a0, a1, a2, a3, b0, b1);
        }
    }
    int row_lo = row0 + warp * 16 + gid;
    int row_hi = row_lo + 8;
    float dd_lo = (row_lo < n) ? dis[row_lo] : 1.f;
    float dd_hi = (row_hi < n) ? dis[row_hi] : 1.f;
#pragma unroll
    for (int t = 0; t < 8; t++) {
        int colp = t * 4 + tig;
        if (row_lo < n)
            ((__half2*)outh)[(size_t)row_lo * 32 + colp] =
                __floats2half2_rn(c[t][0] * dd_lo, c[t][1] * dd_lo);
        if (row_hi < n)
            ((__half2*)outh)[(size_t)row_hi * 32 + colp] =
                __floats2half2_rn(c[t][2] * dd_hi, c[t][3] * dd_hi);
    }
}

// ---------------- launch ----------------
extern "C" void kernel_launch(void* const* d_in, const int* in_sizes, int n_in,
                              void* d_out, int out_size) {
    const float* x      = (const float*)d_in[0];
    const int*   ei     = (const int*)d_in[1];
    const float* gcn1_w = (const float*)d_in[2];
    const float* gcn1_b = (const float*)d_in[3];
    const float* s1lw   = (const float*)d_in[4];
    const float* s1lb   = (const float*)d_in[5];
    const float* s1rw   = (const float*)d_in[6];
    const float* s2lw   = (const float*)d_in[7];
    const float* s2lb   = (const float*)d_in[8];
    const float* s2rw   = (const float*)d_in[9];
    const float* linw   = (const float*)d_in[10];
    const float* linb   = (const float*)d_in[11];
    const float* gcn2_w = (const float*)d_in[12];
    const float* gcn2_b = (const float*)d_in[13];

    int n = in_sizes[0] / 64;
    int E = in_sizes[1] / 2;
    const int* src = ei;
    const int* dst = ei + E;

    int *degi, *rowptr, *cursor, *csr, *scanctr, *stat;
    float *dis;
    __half *hA, *hB, *hC, *hM;
    cudaGetSymbolAddress((void**)&degi, g_degi);
    cudaGetSymbolAddress((void**)&dis, g_dis);
    cudaGetSymbolAddress((void**)&rowptr, g_rowptr);
    cudaGetSymbolAddress((void**)&cursor, g_cursor);
    cudaGetSymbolAddress((void**)&csr, g_csr);
    cudaGetSymbolAddress((void**)&scanctr, g_scan_ctr);
    cudaGetSymbolAddress((void**)&stat, g_stat);
    cudaGetSymbolAddress((void**)&hA, g_hA);
    cudaGetSymbolAddress((void**)&hB, g_hB);
    cudaGetSymbolAddress((void**)&hC, g_hC);
    cudaGetSymbolAddress((void**)&hM, g_hM);

    const int SAGE_SMEM = 17408 + 2 * 18432;    // 54272
    const int LG_SMEM   = 2 * 9216 + 2 * 18432; // 55296
    cudaFuncSetAttribute(sage_h_kernel<true>,  cudaFuncAttributeMaxDynamicSharedMemorySize, SAGE_SMEM);
    cudaFuncSetAttribute(sage_h_kernel<false>, cudaFuncAttributeMaxDynamicSharedMemorySize, SAGE_SMEM);
    cudaFuncSetAttribute(lin_gcn2_kernel, cudaFuncAttributeMaxDynamicSharedMemorySize, LG_SMEM);

    static cudaStream_t s2 = nullptr;
    static cudaEvent_t evFork = nullptr, evDis = nullptr, evJoin = nullptr;
    static cudaEvent_t evP1 = nullptr, evQ1 = nullptr, evP2 = nullptr, evQ2 = nullptr;
    if (!s2) {
        cudaStreamCreateWithFlags(&s2, cudaStreamNonBlocking);
        cudaEventCreateWithFlags(&evFork, cudaEventDisableTiming);
        cudaEventCreateWithFlags(&evDis, cudaEventDisableTiming);
        cudaEventCreateWithFlags(&evJoin, cudaEventDisableTiming);
        cudaEventCreateWithFlags(&evP1, cudaEventDisableTiming);
        cudaEventCreateWithFlags(&evQ1, cudaEventDisableTiming);
        cudaEventCreateWithFlags(&evP2, cudaEventDisableTiming);
        cudaEventCreateWithFlags(&evQ2, cudaEventDisableTiming);
    }

    const int GEMM_GRID = (n + 127) / 128;
    const int NB = (n + 511) / 512;

    // chunk split (128-aligned)
    int nh = ((n / 2 + 127) / 128) * 128;
    if (nh > n) nh = n;
    int n1 = n - nh;
    const int GA0 = (nh + 31) / 32, GA1 = (n1 + 31) / 32;
    const int GS0 = (nh + 127) / 128, GS1 = (n1 + 127) / 128;
    const int GFULL = (n + 31) / 32;

    // ---- fork: CSR build on s2 ----
    cudaEventRecord(evFork, 0);
    cudaStreamWaitEvent(s2, evFork, 0);

    cudaMemsetAsync(degi, 0, n * sizeof(int), s2);
    cudaMemsetAsync(scanctr, 0, sizeof(int), s2);
    cudaMemsetAsync(stat, 0, 256 * sizeof(int), s2);
    deg_count_kernel<<<(E + 255) / 256, 256, 0, s2>>>(dst, E, degi);
    scan_lb_kernel<<<NB, 512, 0, s2>>>(degi, rowptr, cursor, dis, n, E);
    cudaEventRecord(evDis, s2);
    fill_csr_kernel<<<(E + 255) / 256, 256, 0, s2>>>(src, dst, cursor, csr, E);
    cudaEventRecord(evJoin, s2);

    // ---- layer 0 matmul (prescaled by dis): z = (x @ gcn1_w) * dis -> hA ----
    cudaStreamWaitEvent(0, evDis, 0);
    gemm_h_kernel<false, false, true><<<GEMM_GRID, 256>>>(x, gcn1_w, nullptr, dis, hA, n);

    cudaStreamWaitEvent(0, evJoin, 0);

    // ---- layer 0: GCN1 + relu -> hB (full) ----
    gather_kernel<true, true, false><<<GFULL, 256>>>(rowptr, csr, hA, dis, gcn1_b, nullptr, hB, 0, n);

    // ---- layer 1: SAGE1, chunk-pipelined ----
    gather_kernel<false, false, false><<<GA0, 256>>>(rowptr, csr, hB, dis, nullptr, nullptr, hM, 0, nh);
    cudaEventRecord(evP1, 0);
    cudaStreamWaitEvent(s2, evP1, 0);
    if (n1 > 0)
        gather_kernel<false, false, false><<<GA1, 256, 0, s2>>>(rowptr, csr, hB, dis, nullptr, nullptr, hM, nh, n1);
    cudaEventRecord(evQ1, s2);
    sage_h_kernel<true><<<GS0, 256, SAGE_SMEM>>>(hM, hB, s1lw, s1lb, s1rw, hA, 0, nh, n);
    cudaStreamWaitEvent(0, evQ1, 0);
    if (n1 > 0)
        sage_h_kernel<true><<<GS1, 256, SAGE_SMEM>>>(hM, hB, s1lw, s1lb, s1rw, hA, nh, n1, n);

    // ---- layer 2: SAGE2, chunk-pipelined ----
    gather_kernel<false, false, false><<<GA0, 256>>>(rowptr, csr, hA, dis, nullptr, nullptr, hM, 0, nh);
    cudaEventRecord(evP2, 0);
    cudaStreamWaitEvent(s2, evP2, 0);
    if (n1 > 0)
        gather_kernel<false, false, false><<<GA1, 256, 0, s2>>>(rowptr, csr, hA, dis, nullptr, nullptr, hM, nh, n1);
    cudaEventRecord(evQ2, s2);
    sage_h_kernel<false><<<GS0, 256, SAGE_SMEM>>>(hM, hA, s2lw, s2lb, s2rw, hC, 0, nh, n);
    cudaStreamWaitEvent(0, evQ2, 0);
    if (n1 > 0)
        sage_h_kernel<false><<<GS1, 256, SAGE_SMEM>>>(hM, hA, s2lw, s2lb, s2rw, hC, nh, n1, n);

    // ---- lin + relu + gcn2 matmul fused, prescaled by dis -> hB ----
    lin_gcn2_kernel<<<GEMM_GRID, 256, LG_SMEM>>>(hC, linw, linb, gcn2_w, dis, hB, n);

    // ---- layer 3: final GCN gather -> d_out (fp32) ----
    gather_kernel<true, false, true><<<GFULL, 256>>>(rowptr, csr, hB, dis, gcn2_b, (float*)d_out, nullptr, 0, n);
}

// round 14
// speedup vs baseline: 1.3912x; 1.3912x over previous
#include <cuda_runtime.h>
#include <cuda_bf16.h>
#include <cuda_fp16.h>

#define NMAX 100000
#define EMAX 1250000
#define DD 64
#define WSTRIDE 72
#define WMAT (64 * WSTRIDE)   // 4608 halves per transposed matrix

// ---------------- scratch ----------------
__device__ int    g_degi[NMAX];
__device__ float  g_dis[NMAX];
__device__ int    g_rowptr[NMAX + 1];
__device__ int    g_cursor[NMAX];
__device__ int    g_csr[EMAX];
__device__ int    g_blocksums[512];
__device__ __half g_wt[7][WMAT];     // transposed fp16 weights: [mat][col*72 + k]
__device__ __half g_hA[(size_t)NMAX * DD];
__device__ __half g_hB[(size_t)NMAX * DD];
__device__ __half g_hC[(size_t)NMAX * DD];
__device__ __half g_hM[(size_t)NMAX * DD];

// ---------------- fp16 mma helper ----------------
__device__ __forceinline__ void mma16(float c[4], unsigned a0, unsigned a1, unsigned a2,
                                      unsigned a3, unsigned b0, unsigned b1) {
    asm("mma.sync.aligned.m16n8k16.row.col.f32.f16.f16.f32 "
        "{%0,%1,%2,%3},{%4,%5,%6,%7},{%8,%9},{%0,%1,%2,%3};"
        : "+f"(c[0]), "+f"(c[1]), "+f"(c[2]), "+f"(c[3])
        : "r"(a0), "r"(a1), "r"(a2), "r"(a3), "r"(b0), "r"(b1));
}

__device__ __forceinline__ void acc8(float4& a, float4& b, uint4 u, float w) {
    float2 f0 = __half22float2(*reinterpret_cast<const __half2*>(&u.x));
    float2 f1 = __half22float2(*reinterpret_cast<const __half2*>(&u.y));
    float2 f2 = __half22float2(*reinterpret_cast<const __half2*>(&u.z));
    float2 f3 = __half22float2(*reinterpret_cast<const __half2*>(&u.w));
    a.x = fmaf(f0.x, w, a.x); a.y = fmaf(f0.y, w, a.y);
    a.z = fmaf(f1.x, w, a.z); a.w = fmaf(f1.y, w, a.w);
    b.x = fmaf(f2.x, w, b.x); b.y = fmaf(f2.y, w, b.y);
    b.z = fmaf(f3.x, w, b.z); b.w = fmaf(f3.y, w, b.w);
}
__device__ __forceinline__ void acc8s(float4& a, float4& b, uint4 u) {
    float2 f0 = __half22float2(*reinterpret_cast<const __half2*>(&u.x));
    float2 f1 = __half22float2(*reinterpret_cast<const __half2*>(&u.y));
    float2 f2 = __half22float2(*reinterpret_cast<const __half2*>(&u.z));
    float2 f3 = __half22float2(*reinterpret_cast<const __half2*>(&u.w));
    a.x += f0.x; a.y += f0.y; a.z += f1.x; a.w += f1.y;
    b.x += f2.x; b.y += f2.y; b.z += f3.x; b.w += f3.y;
}
__device__ __forceinline__ unsigned packh2(float x, float y) {
    __half2 h = __floats2half2_rn(x, y);
    return *reinterpret_cast<unsigned*>(&h);
}
__device__ __forceinline__ uint4 pack_h8(float4 a, float4 b) {
    uint4 u;
    u.x = packh2(a.x, a.y); u.y = packh2(a.z, a.w);
    u.z = packh2(b.x, b.y); u.w = packh2(b.z, b.w);
    return u;
}
__device__ __forceinline__ uint2 pack_h4(float4 v) {
    uint2 u;
    u.x = packh2(v.x, v.y); u.y = packh2(v.z, v.w);
    return u;
}

// ---------------- weight pre-convert: g_wt[m][c*72+k] = half(Wm[k*64+c]) ----------------
__global__ void convw_kernel(const float* __restrict__ w0, const float* __restrict__ w1,
                             const float* __restrict__ w2, const float* __restrict__ w3,
                             const float* __restrict__ w4, const float* __restrict__ w5,
                             const float* __restrict__ w6) {
    int i = blockIdx.x * blockDim.x + threadIdx.x;
    if (i >= 7 * 4096) return;
    int m = i >> 12, idx = i & 4095;
    int k = idx >> 6, c = idx & 63;
    const float* W = (m == 0) ? w0 : (m == 1) ? w1 : (m == 2) ? w2 : (m == 3) ? w3
                   : (m == 4) ? w4 : (m == 5) ? w5 : w6;
    g_wt[m][c * WSTRIDE + k] = __float2half(W[idx]);
}

// ---------------- degree ----------------
__global__ void deg_count_kernel(const int* __restrict__ dst, int E, int* __restrict__ degi) {
    int i = blockIdx.x * blockDim.x + threadIdx.x;
    if (i < E) atomicAdd(&degi[dst[i]], 1);
}

// ---------------- exclusive scan, fused dis ----------------
__global__ void scan1_kernel(const int* __restrict__ cnt, int* __restrict__ out,
                             int* __restrict__ bsums, float* __restrict__ dis, int n) {
    __shared__ int s[512];
    int i = blockIdx.x * 512 + threadIdx.x;
    int v = (i < n) ? cnt[i] : 0;
    if (i < n) dis[i] = rsqrtf((float)v + 1.0f);
    s[threadIdx.x] = v;
    __syncthreads();
    for (int off = 1; off < 512; off <<= 1) {
        int t = (threadIdx.x >= off) ? s[threadIdx.x - off] : 0;
        __syncthreads();
        s[threadIdx.x] += t;
        __syncthreads();
    }
    if (i < n) out[i] = s[threadIdx.x] - v;
    if (threadIdx.x == 511) bsums[blockIdx.x] = s[511];
}
__global__ void scan2_kernel(int* __restrict__ bsums, int nb) {
    __shared__ int s[512];
    int v = (threadIdx.x < nb) ? bsums[threadIdx.x] : 0;
    s[threadIdx.x] = v;
    __syncthreads();
    for (int off = 1; off < 512; off <<= 1) {
        int t = (threadIdx.x >= off) ? s[threadIdx.x - off] : 0;
        __syncthreads();
        s[threadIdx.x] += t;
        __syncthreads();
    }
    if (threadIdx.x < nb) bsums[threadIdx.x] = s[threadIdx.x] - v;
}
__global__ void scan3_kernel(int* __restrict__ rowptr, const int* __restrict__ bsums,
                             int* __restrict__ cursor, int n, int E) {
    int i = blockIdx.x * 512 + threadIdx.x;
    if (i < n) {
        int v = rowptr[i] + bsums[blockIdx.x];
        rowptr[i] = v;
        cursor[i] = v;
    }
    if (i == n) rowptr[n] = E;
}
__global__ void fill_csr_kernel(const int* __restrict__ src, const int* __restrict__ dst,
                                int* __restrict__ cursor, int* __restrict__ csr, int E) {
    int i = blockIdx.x * blockDim.x + threadIdx.x;
    if (i < E) {
        int pos = atomicAdd(&cursor[dst[i]], 1);
        csr[pos] = src[i];
    }
}

// ---------------- gather (CSR), 8 lanes/node, LDG.128 rows (R11-proven) ----------------
template <bool GCN, bool RELU, bool OUTF32>
__global__ void __launch_bounds__(256) gather_kernel(
    const int* __restrict__ rowptr, const int* __restrict__ csr,
    const __half* __restrict__ xwh, const float* __restrict__ dis,
    const float* __restrict__ bias, float* __restrict__ outf,
    __half* __restrict__ outh, int n) {
    int node = blockIdx.x * 32 + (threadIdx.x >> 3);
    int q = threadIdx.x & 7;
    if (node >= n) return;
    int beg = rowptr[node], end = rowptr[node + 1];
    float4 aL = make_float4(0.f, 0.f, 0.f, 0.f);
    float4 aH = make_float4(0.f, 0.f, 0.f, 0.f);
    const uint4* __restrict__ xv4 = (const uint4*)xwh;
    int e = beg;
    for (; e + 3 < end; e += 4) {
        int s0 = csr[e], s1 = csr[e + 1], s2 = csr[e + 2], s3 = csr[e + 3];
        uint4 u0 = xv4[s0 * 8 + q];
        uint4 u1 = xv4[s1 * 8 + q];
        uint4 u2 = xv4[s2 * 8 + q];
        uint4 u3 = xv4[s3 * 8 + q];
        if (GCN) {
            float w0 = dis[s0], w1 = dis[s1], w2 = dis[s2], w3 = dis[s3];
            acc8(aL, aH, u0, w0); acc8(aL, aH, u1, w1);
            acc8(aL, aH, u2, w2); acc8(aL, aH, u3, w3);
        } else {
            acc8s(aL, aH, u0); acc8s(aL, aH, u1);
            acc8s(aL, aH, u2); acc8s(aL, aH, u3);
        }
    }
    for (; e < end; e++) {
        int s = csr[e];
        uint4 u = xv4[s * 8 + q];
        if (GCN) acc8(aL, aH, u, dis[s]);
        else     acc8s(aL, aH, u);
    }
    if (GCN) {
        float dd = dis[node];
        float d2 = dd * dd;
        float4 xL = make_float4(0.f, 0.f, 0.f, 0.f);
        float4 xH = make_float4(0.f, 0.f, 0.f, 0.f);
        acc8(xL, xH, xv4[node * 8 + q], 1.0f);
        float4 b0 = ((const float4*)bias)[q * 2];
        float4 b1 = ((const float4*)bias)[q * 2 + 1];
        aL.x = fmaf(aL.x, dd, fmaf(xL.x, d2, b0.x));
        aL.y = fmaf(aL.y, dd, fmaf(xL.y, d2, b0.y));
        aL.z = fmaf(aL.z, dd, fmaf(xL.z, d2, b0.z));
        aL.w = fmaf(aL.w, dd, fmaf(xL.w, d2, b0.w));
        aH.x = fmaf(aH.x, dd, fmaf(xH.x, d2, b1.x));
        aH.y = fmaf(aH.y, dd, fmaf(xH.y, d2, b1.y));
        aH.z = fmaf(aH.z, dd, fmaf(xH.z, d2, b1.z));
        aH.w = fmaf(aH.w, dd, fmaf(xH.w, d2, b1.w));
        if (RELU) {
            aL.x = fmaxf(aL.x, 0.f); aL.y = fmaxf(aL.y, 0.f);
            aL.z = fmaxf(aL.z, 0.f); aL.w = fmaxf(aL.w, 0.f);
            aH.x = fmaxf(aH.x, 0.f); aH.y = fmaxf(aH.y, 0.f);
            aH.z = fmaxf(aH.z, 0.f); aH.w = fmaxf(aH.w, 0.f);
        }
    } else {
        float dinv = 1.0f / fmaxf((float)(end - beg), 1.0f);
        aL.x *= dinv; aL.y *= dinv; aL.z *= dinv; aL.w *= dinv;
        aH.x *= dinv; aH.y *= dinv; aH.z *= dinv; aH.w *= dinv;
    }
    if (OUTF32) {
        ((float4*)outf)[node * 16 + q * 2]     = aL;
        ((float4*)outf)[node * 16 + q * 2 + 1] = aH;
    } else {
        ((uint4*)outh)[node * 8 + q] = pack_h8(aL, aH);
    }
}

// ---------------- fp16 tensor-core GEMM (pre-transposed fp16 W): out = X @ Wt -> fp16 ----------------
__global__ void __launch_bounds__(256) gemm_h_kernel(
    const float* __restrict__ Xf, const __half* __restrict__ Wg,
    __half* __restrict__ outh, int n) {
    __shared__ __half Wt[WMAT];
    __shared__ __half Xh[128 * 72];
    int tid = threadIdx.x;
    int row0 = blockIdx.x * 128;

    for (int i = tid; i < WMAT / 8; i += 256)
        ((uint4*)Wt)[i] = ((const uint4*)Wg)[i];
    for (int j = tid; j < 2048; j += 256) {
        int r = j >> 4, cg = j & 15;
        uint2 u = make_uint2(0u, 0u);
        if (row0 + r < n) {
            float4 v = ((const float4*)Xf)[(size_t)(row0 + r) * 16 + cg];
            u = pack_h4(v);
        }
        *reinterpret_cast<uint2*>(&Xh[r * 72 + cg * 4]) = u;
    }
    __syncthreads();

    int warp = tid >> 5;
    int lane = tid & 31;
    int gid = lane >> 2;
    int tig = lane & 3;
    int rlo = warp * 16 + gid;

    float c[8][4];
#pragma unroll
    for (int t = 0; t < 8; t++)
#pragma unroll
        for (int j = 0; j < 4; j++) c[t][j] = 0.f;

#pragma unroll
    for (int ks = 0; ks < 4; ks++) {
        int k0 = ks * 16;
        unsigned a0 = *reinterpret_cast<const unsigned*>(&Xh[rlo * 72 + k0 + tig * 2]);
        unsigned a1 = *reinterpret_cast<const unsigned*>(&Xh[(rlo + 8) * 72 + k0 + tig * 2]);
        unsigned a2 = *reinterpret_cast<const unsigned*>(&Xh[rlo * 72 + k0 + 8 + tig * 2]);
        unsigned a3 = *reinterpret_cast<const unsigned*>(&Xh[(rlo + 8) * 72 + k0 + 8 + tig * 2]);
#pragma unroll
        for (int t = 0; t < 8; t++) {
            int col = t * 8 + gid;
            unsigned b0 = *reinterpret_cast<const unsigned*>(&Wt[col * 72 + k0 + tig * 2]);
            unsigned b1 = *reinterpret_cast<const unsigned*>(&Wt[col * 72 + k0 + 8 + tig * 2]);
            mma16(c[t], a0, a1, a2, a3, b0, b1);
        }
    }

#pragma unroll
    for (int t = 0; t < 8; t++) {
        int colp = t * 4 + tig;
        int row_lo = row0 + warp * 16 + gid;
        int row_hi = row_lo + 8;
        if (row_lo < n)
            ((__half2*)outh)[(size_t)row_lo * 32 + colp] = __floats2half2_rn(c[t][0], c[t][1]);
        if (row_hi < n)
            ((__half2*)outh)[(size_t)row_hi * 32 + colp] = __floats2half2_rn(c[t][2], c[t][3]);
    }
}

// ---------------- fp16 SAGE (pre-transposed Wl/Wr): act(M@Wl + bl + H@Wr + H) -> fp16 ----------------
// dyn smem: Wls 9216 + Wrs 9216 + Mh 18432 + Hh 18432 = 55296
template <bool RELU>
__global__ void __launch_bounds__(256) sage_h_kernel(
    const __half* __restrict__ M, const __half* __restrict__ H,
    const __half* __restrict__ Wlg, const float* __restrict__ bl,
    const __half* __restrict__ Wrg, __half* __restrict__ outh, int n) {
    extern __shared__ char smraw[];
    __half* Wls = (__half*)smraw;
    __half* Wrs = (__half*)(smraw + 9216);
    __half* Mh  = (__half*)(smraw + 18432);
    __half* Hh  = (__half*)(smraw + 18432 + 18432);
    int tid = threadIdx.x;
    int row0 = blockIdx.x * 128;

    for (int i = tid; i < WMAT / 8; i += 256) {
        ((uint4*)Wls)[i] = ((const uint4*)Wlg)[i];
        ((uint4*)Wrs)[i] = ((const uint4*)Wrg)[i];
    }
    for (int j = tid; j < 2048; j += 256) {
        int r = j >> 4, cg = j & 15;
        uint2 um = make_uint2(0u, 0u), uh = um;
        if (row0 + r < n) {
            um = ((const uint2*)M)[(size_t)(row0 + r) * 16 + cg];
            uh = ((const uint2*)H)[(size_t)(row0 + r) * 16 + cg];
        }
        *reinterpret_cast<uint2*>(&Mh[r * 72 + cg * 4]) = um;
        *reinterpret_cast<uint2*>(&Hh[r * 72 + cg * 4]) = uh;
    }
    __syncthreads();

    int warp = tid >> 5;
    int lane = tid & 31;
    int gid = lane >> 2;
    int tig = lane & 3;
    int rlo = warp * 16 + gid;

    float c[8][4];
#pragma unroll
    for (int t = 0; t < 8; t++)
#pragma unroll
        for (int j = 0; j < 4; j++) c[t][j] = 0.f;

#pragma unroll
    for (int ks = 0; ks < 8; ks++) {
        const __half* A = (ks < 4) ? Mh : Hh;
        const __half* Ws = (ks < 4) ? Wls : Wrs;
        int k0 = (ks & 3) * 16;
        unsigned a0 = *reinterpret_cast<const unsigned*>(&A[rlo * 72 + k0 + tig * 2]);
        unsigned a1 = *reinterpret_cast<const unsigned*>(&A[(rlo + 8) * 72 + k0 + tig * 2]);
        unsigned a2 = *reinterpret_cast<const unsigned*>(&A[rlo * 72 + k0 + 8 + tig * 2]);
        unsigned a3 = *reinterpret_cast<const unsigned*>(&A[(rlo + 8) * 72 + k0 + 8 + tig * 2]);
#pragma unroll
        for (int t = 0; t < 8; t++) {
            int col = t * 8 + gid;
            unsigned b0 = *reinterpret_cast<const unsigned*>(&Ws[col * 72 + k0 + tig * 2]);
            unsigned b1 = *reinterpret_cast<const unsigned*>(&Ws[col * 72 + k0 + 8 + tig * 2]);
            mma16(c[t], a0, a1, a2, a3, b0, b1);
        }
    }

#pragma unroll
    for (int t = 0; t < 8; t++) {
        int colp = t * 4 + tig;
        int col = t * 8 + tig * 2;
        float2 bb = ((const float2*)bl)[colp];
        int rl = warp * 16 + gid;
        int row_lo = row0 + rl;
        int row_hi = row_lo + 8;
        if (row_lo < n) {
            float2 hres = __half22float2(*reinterpret_cast<const __half2*>(&Hh[rl * 72 + col]));
            float ox = c[t][0] + bb.x + hres.x, oy = c[t][1] + bb.y + hres.y;
            if (RELU) { ox = fmaxf(ox, 0.f); oy = fmaxf(oy, 0.f); }
            ((__half2*)outh)[(size_t)row_lo * 32 + colp] = __floats2half2_rn(ox, oy);
        }
        if (row_hi < n) {
            float2 hres = __half22float2(*reinterpret_cast<const __half2*>(&Hh[(rl + 8) * 72 + col]));
            float ox = c[t][2] + bb.x + hres.x, oy = c[t][3] + bb.y + hres.y;
            if (RELU) { ox = fmaxf(ox, 0.f); oy = fmaxf(oy, 0.f); }
            ((__half2*)outh)[(size_t)row_hi * 32 + colp] = __floats2half2_rn(ox, oy);
        }
    }
}

// ---------------- fused lin+gcn2 (pre-transposed): out = (relu(X@W1 + b1)) @ W2 -> fp16 ----------------
// dyn smem: W1t 9216 + W2t 9216 + Xh 18432 + Th 18432 = 55296
__global__ void __launch_bounds__(256) lin_gcn2_kernel(
    const __half* __restrict__ Xin, const __half* __restrict__ W1g,
    const float* __restrict__ b1, const __half* __restrict__ W2g,
    __half* __restrict__ outh, int n) {
    extern __shared__ char smraw[];
    __half* W1t = (__half*)smraw;
    __half* W2t = (__half*)(smraw + 9216);
    __half* Xh  = (__half*)(smraw + 18432);
    __half* Th  = (__half*)(smraw + 18432 + 18432);
    int tid = threadIdx.x;
    int row0 = blockIdx.x * 128;

    for (int i = tid; i < WMAT / 8; i += 256) {
        ((uint4*)W1t)[i] = ((const uint4*)W1g)[i];
        ((uint4*)W2t)[i] = ((const uint4*)W2g)[i];
    }
    for (int j = tid; j < 2048; j += 256) {
        int r = j >> 4, cg = j & 15;
        uint2 u = make_uint2(0u, 0u);
        if (row0 + r < n) u = ((const uint2*)Xin)[(size_t)(row0 + r) * 16 + cg];
        *reinterpret_cast<uint2*>(&Xh[r * 72 + cg * 4]) = u;
    }
    __syncthreads();

    int warp = tid >> 5;
    int lane = tid & 31;
    int gid = lane >> 2;
    int tig = lane & 3;
    int rlo = warp * 16 + gid;

    float c[8][4];
#pragma unroll
    for (int t = 0; t < 8; t++)
#pragma unroll
        for (int j = 0; j < 4; j++) c[t][j] = 0.f;

#pragma unroll
    for (int ks = 0; ks < 4; ks++) {
        int k0 = ks * 16;
        unsigned a0 = *reinterpret_cast<const unsigned*>(&Xh[rlo * 72 + k0 + tig * 2]);
        unsigned a1 = *reinterpret_cast<const unsigned*>(&Xh[(rlo + 8) * 72 + k0 + tig * 2]);
        unsigned a2 = *reinterpret_cast<const unsigned*>(&Xh[rlo * 72 + k0 + 8 + tig * 2]);
        unsigned a3 = *reinterpret_cast<const unsigned*>(&Xh[(rlo + 8) * 72 + k0 + 8 + tig * 2]);
#pragma unroll
        for (int t = 0; t < 8; t++) {
            int col = t * 8 + gid;
            unsigned b0 = *reinterpret_cast<const unsigned*>(&W1t[col * 72 + k0 + tig * 2]);
            unsigned b1 = *reinterpret_cast<const unsigned*>(&W1t[col * 72 + k0 + 8 + tig * 2]);
            mma16(c[t], a0, a1, a2, a3, b0, b1);
        }
    }
#pragma unroll
    for (int t = 0; t < 8; t++) {
        int colp = t * 4 + tig;
        int col = t * 8 + tig * 2;
        float2 bb = ((const float2*)b1)[colp];
        int rl = warp * 16 + gid;
        float ox0 = fmaxf(c[t][0] + bb.x, 0.f), oy0 = fmaxf(c[t][1] + bb.y, 0.f);
        float ox1 = fmaxf(c[t][2] + bb.x, 0.f), oy1 = fmaxf(c[t][3] + bb.y, 0.f);
        *reinterpret_cast<__half2*>(&Th[rl * 72 + col])       = __floats2half2_rn(ox0, oy0);
        *reinterpret_cast<__half2*>(&Th[(rl + 8) * 72 + col]) = __floats2half2_rn(ox1, oy1);
    }
    __syncthreads();

#pragma unroll
    for (int t = 0; t < 8; t++)
#pragma unroll
        for (int j = 0; j < 4; j++) c[t][j] = 0.f;
#pragma unroll
    for (int ks = 0; ks < 4; ks++) {
        int k0 = ks * 16;
        unsigned a0 = *reinterpret_cast<const unsigned*>(&Th[rlo * 72 + k0 + tig * 2]);
        unsigned a1 = *reinterpret_cast<const unsigned*>(&Th[(rlo + 8) * 72 + k0 + tig * 2]);
        unsigned a2 = *reinterpret_cast<const unsigned*>(&Th[rlo * 72 + k0 + 8 + tig * 2]);
        unsigned a3 = *reinterpret_cast<const unsigned*>(&Th[(rlo + 8) * 72 + k0 + 8 + tig * 2]);
#pragma unroll
        for (int t = 0; t < 8; t++) {
            int col = t * 8 + gid;
            unsigned b0 = *reinterpret_cast<const unsigned*>(&W2t[col * 72 + k0 + tig * 2]);
            unsigned b1 = *reinterpret_cast<const unsigned*>(&W2t[col * 72 + k0 + 8 + tig * 2]);
            mma16(c[t], a0, a1, a2, a3, b0, b1);
        }
    }
#pragma unroll
    for (int t = 0; t < 8; t++) {
        int colp = t * 4 + tig;
        int row_lo = row0 + warp * 16 + gid;
        int row_hi = row_lo + 8;
        if (row_lo < n)
            ((__half2*)outh)[(size_t)row_lo * 32 + colp] = __floats2half2_rn(c[t][0], c[t][1]);
        if (row_hi < n)
            ((__half2*)outh)[(size_t)row_hi * 32 + colp] = __floats2half2_rn(c[t][2], c[t][3]);
    }
}

// ---------------- launch ----------------
extern "C" void kernel_launch(void* const* d_in, const int* in_sizes, int n_in,
                              void* d_out, int out_size) {
    const float* x      = (const float*)d_in[0];
    const int*   ei     = (const int*)d_in[1];
    const float* gcn1_w = (const float*)d_in[2];
    const float* gcn1_b = (const float*)d_in[3];
    const float* s1lw   = (const float*)d_in[4];
    const float* s1lb   = (const float*)d_in[5];
    const float* s1rw   = (const float*)d_in[6];
    const float* s2lw   = (const float*)d_in[7];
    const float* s2lb   = (const float*)d_in[8];
    const float* s2rw   = (const float*)d_in[9];
    const float* linw   = (const float*)d_in[10];
    const float* linb   = (const float*)d_in[11];
    const float* gcn2_w = (const float*)d_in[12];
    const float* gcn2_b = (const float*)d_in[13];

    int n = in_sizes[0] / 64;
    int E = in_sizes[1] / 2;
    const int* src = ei;
    const int* dst = ei + E;

    int *degi, *rowptr, *cursor, *csr, *bsums;
    float *dis;
    __half *hA, *hB, *hC, *hM, *wt;
    cudaGetSymbolAddress((void**)&degi, g_degi);
    cudaGetSymbolAddress((void**)&dis, g_dis);
    cudaGetSymbolAddress((void**)&rowptr, g_rowptr);
    cudaGetSymbolAddress((void**)&cursor, g_cursor);
    cudaGetSymbolAddress((void**)&csr, g_csr);
    cudaGetSymbolAddress((void**)&bsums, g_blocksums);
    cudaGetSymbolAddress((void**)&hA, g_hA);
    cudaGetSymbolAddress((void**)&hB, g_hB);
    cudaGetSymbolAddress((void**)&hC, g_hC);
    cudaGetSymbolAddress((void**)&hM, g_hM);
    cudaGetSymbolAddress((void**)&wt, g_wt);

    const __half* wt_gcn1 = wt + 0 * WMAT;
    const __half* wt_s1l  = wt + 1 * WMAT;
    const __half* wt_s1r  = wt + 2 * WMAT;
    const __half* wt_s2l  = wt + 3 * WMAT;
    const __half* wt_s2r  = wt + 4 * WMAT;
    const __half* wt_lin  = wt + 5 * WMAT;
    const __half* wt_gcn2 = wt + 6 * WMAT;

    const int SAGE_SMEM = 2 * 9216 + 2 * 18432;  // 55296
    const int LG_SMEM   = 2 * 9216 + 2 * 18432;  // 55296
    cudaFuncSetAttribute(sage_h_kernel<true>,  cudaFuncAttributeMaxDynamicSharedMemorySize, SAGE_SMEM);
    cudaFuncSetAttribute(sage_h_kernel<false>, cudaFuncAttributeMaxDynamicSharedMemorySize, SAGE_SMEM);
    cudaFuncSetAttribute(lin_gcn2_kernel, cudaFuncAttributeMaxDynamicSharedMemorySize, LG_SMEM);

    static cudaStream_t s2 = nullptr;
    static cudaEvent_t evFork = nullptr, evW = nullptr, evJoin = nullptr;
    if (!s2) {
        cudaStreamCreateWithFlags(&s2, cudaStreamNonBlocking);
        cudaEventCreateWithFlags(&evFork, cudaEventDisableTiming);
        cudaEventCreateWithFlags(&evW, cudaEventDisableTiming);
        cudaEventCreateWithFlags(&evJoin, cudaEventDisableTiming);
    }

    const int GEMM_GRID = (n + 127) / 128;
    const int GATH_GRID = (n + 31) / 32;
    const int NB = (n + 511) / 512;

    // ---- fork: weight convert + CSR build on s2 ----
    cudaEventRecord(evFork, 0);
    cudaStreamWaitEvent(s2, evFork, 0);

    convw_kernel<<<(7 * 4096 + 255) / 256, 256, 0, s2>>>(gcn1_w, s1lw, s1rw, s2lw, s2rw, linw, gcn2_w);
    cudaEventRecord(evW, s2);
    cudaMemsetAsync(degi, 0, n * sizeof(int), s2);
    deg_count_kernel<<<(E + 255) / 256, 256, 0, s2>>>(dst, E, degi);
    scan1_kernel<<<NB, 512, 0, s2>>>(degi, rowptr, bsums, dis, n);
    scan2_kernel<<<1, 512, 0, s2>>>(bsums, NB);
    scan3_kernel<<<(n + 512) / 512, 512, 0, s2>>>(rowptr, bsums, cursor, n, E);
    fill_csr_kernel<<<(E + 255) / 256, 256, 0, s2>>>(src, dst, cursor, csr, E);
    cudaEventRecord(evJoin, s2);

    // ---- layer 0 matmul: xw = x @ gcn1_w -> hA (waits only on weight convert) ----
    cudaStreamWaitEvent(0, evW, 0);
    gemm_h_kernel<<<GEMM_GRID, 256>>>(x, wt_gcn1, hA, n);

    cudaStreamWaitEvent(0, evJoin, 0);

    // ---- layer 0: GCN1 + relu -> hB ----
    gather_kernel<true, true, false><<<GATH_GRID, 256>>>(rowptr, csr, hA, dis, gcn1_b, nullptr, hB, n);

    // ---- layer 1: SAGE1 (mean gather + combine + relu) -> hA ----
    gather_kernel<false, false, false><<<GATH_GRID, 256>>>(rowptr, csr, hB, dis, nullptr, nullptr, hM, n);
    sage_h_kernel<true><<<GEMM_GRID, 256, SAGE_SMEM>>>(hM, hB, wt_s1l, s1lb, wt_s1r, hA, n);

    // ---- layer 2: SAGE2 -> hC ----
    gather_kernel<false, false, false><<<GATH_GRID, 256>>>(rowptr, csr, hA, dis, nullptr, nullptr, hM, n);
    sage_h_kernel<false><<<GEMM_GRID, 256, SAGE_SMEM>>>(hM, hA, wt_s2l, s2lb, wt_s2r, hC, n);

    // ---- lin + relu + gcn2 matmul fused -> hB ----
    lin_gcn2_kernel<<<GEMM_GRID, 256, LG_SMEM>>>(hC, wt_lin, linb, wt_gcn2, hB, n);

    // ---- layer 3: final GCN gather -> d_out (fp32) ----
    gather_kernel<true, false, true><<<GATH_GRID, 256>>>(rowptr, csr, hB, dis, gcn2_b, (float*)d_out, nullptr, n);
}